// round 17
// baseline (speedup 1.0000x reference)
#include <cuda_runtime.h>
#include <cuda_fp16.h>
#include <cstdint>

// Batched Newton-Schulz matrix sqrt: 1024 x (128x128 fp32), 5 iterations.
// FP16 mma.sync (m16n8k16, fp32 accum), triangular outputs + mirror.
// 256-thread CTAs, 2 CTAs/SM. m64n32 column-panel tasks (192 B smem/MMA)
// cut crossbar traffic; per-SMSP unit counts exactly balanced.

#define NMAT 128
#define NT 256
#define PITCH32 68      // u32 words per smem row
#define PITCHB 272      // bytes per smem row (conflict-free)
#define PITCH16 136

__device__ __forceinline__ void mma_f16(float* d, const uint32_t* a,
                                        const uint32_t* b) {
    asm volatile(
        "mma.sync.aligned.m16n8k16.row.col.f32.f16.f16.f32 "
        "{%0,%1,%2,%3}, {%4,%5,%6,%7}, {%8,%9}, {%0,%1,%2,%3};"
        : "+f"(d[0]), "+f"(d[1]), "+f"(d[2]), "+f"(d[3])
        : "r"(a[0]), "r"(a[1]), "r"(a[2]), "r"(a[3]), "r"(b[0]), "r"(b[1]));
}

#define LDSM4(r_, a_)                                                         \
    asm volatile("ldmatrix.sync.aligned.m8n8.x4.shared.b16 {%0,%1,%2,%3}, [%4];" \
                 : "=r"((r_)[0]), "=r"((r_)[1]), "=r"((r_)[2]), "=r"((r_)[3])  \
                 : "r"(a_))

__device__ __forceinline__ uint32_t sp(const void* p) {
    return (uint32_t)__cvta_generic_to_shared(p);
}

__device__ __forceinline__ uint32_t h2pack(float v0, float v1) {
    uint32_t r;
    asm("cvt.rn.f16x2.f32 %0, %1, %2;" : "=r"(r) : "f"(v1), "f"(v0));
    return r;
}

__device__ __forceinline__ void zero4(float a[4][4]) {
#pragma unroll
    for (int i = 0; i < 4; i++)
#pragma unroll
        for (int j = 0; j < 4; j++) a[i][j] = 0.f;
}

// ldmatrix octet addressing (16-bit rows)
__device__ __forceinline__ uint32_t a_off(int r0, int lane) {
    return (uint32_t)((r0 + (lane & 7) + ((lane >> 3) & 1) * 8) * PITCHB +
                      (lane >> 4) * 16);
}
__device__ __forceinline__ uint32_t b_off(int c0, int lane) {
    return (uint32_t)((c0 + (lane & 7) + (lane >> 4) * 8) * PITCHB +
                      ((lane >> 3) & 1) * 16);
}

// m16n32: acc[4][4]
__device__ __forceinline__ void mm16(const uint32_t* P, const uint32_t* Q,
                                     float acc[4][4], int r0, int c0, int lane) {
    const uint32_t pa = sp(P) + a_off(r0, lane);
    uint32_t qb0 = sp(Q) + b_off(c0, lane);
    uint32_t qb1 = qb0 + 16 * PITCHB;
#pragma unroll
    for (int k = 0; k < 8; k++) {
        uint32_t a[4], b[8];
        LDSM4(a, pa + k * 32);
        LDSM4(b, qb0); LDSM4(b + 4, qb1);
        qb0 += 32; qb1 += 32;
#pragma unroll
        for (int ni = 0; ni < 4; ni++) mma_f16(acc[ni], a, b + ni * 2);
    }
}

// m32n32: acc[2][4][4]
__device__ __forceinline__ void mm32(const uint32_t* P, const uint32_t* Q,
                                     float acc[2][4][4], int r0, int c0,
                                     int lane) {
    const uint32_t pa0 = sp(P) + a_off(r0, lane);
    const uint32_t pa1 = sp(P) + a_off(r0 + 16, lane);
    uint32_t qb0 = sp(Q) + b_off(c0, lane);
    uint32_t qb1 = qb0 + 16 * PITCHB;
#pragma unroll
    for (int k = 0; k < 8; k++) {
        uint32_t a0[4], a1[4], b[8];
        LDSM4(a0, pa0 + k * 32);
        LDSM4(a1, pa1 + k * 32);
        LDSM4(b, qb0); LDSM4(b + 4, qb1);
        qb0 += 32; qb1 += 32;
#pragma unroll
        for (int ni = 0; ni < 4; ni++) {
            mma_f16(acc[0][ni], a0, b + ni * 2);
            mma_f16(acc[1][ni], a1, b + ni * 2);
        }
    }
}

// m64n32: acc[4][4][4]; B resident per k-step, A streamed per row-group
__device__ __forceinline__ void mm64(const uint32_t* P, const uint32_t* Q,
                                     float acc[4][4][4], int r0, int c0,
                                     int lane) {
    const uint32_t pa = sp(P) + a_off(r0, lane);
    uint32_t qb0 = sp(Q) + b_off(c0, lane);
    uint32_t qb1 = qb0 + 16 * PITCHB;
#pragma unroll
    for (int k = 0; k < 8; k++) {
        uint32_t b[8];
        LDSM4(b, qb0); LDSM4(b + 4, qb1);
        qb0 += 32; qb1 += 32;
#pragma unroll
        for (int mi = 0; mi < 4; mi++) {
            uint32_t a[4];
            LDSM4(a, pa + (uint32_t)(mi * 16 * PITCHB + k * 32));
#pragma unroll
            for (int ni = 0; ni < 4; ni++) mma_f16(acc[mi][ni], a, b + ni * 2);
        }
    }
}

// v = alpha*acc + beta*I -> fp16 words; optional mirror to transposed pos.
__device__ __forceinline__ void epi_t(const float acc[4][4],
                                      uint32_t* __restrict__ B, float alpha,
                                      float beta, int r0, int c0, int lane,
                                      bool mir) {
    const int qr = lane >> 2, cp = (lane & 3) * 2;
    uint16_t* B16 = (uint16_t*)B;
#pragma unroll
    for (int ni = 0; ni < 4; ni++) {
        const int col = c0 + ni * 8 + cp;
#pragma unroll
        for (int h = 0; h < 2; h++) {
            const int row = r0 + qr + h * 8;
            float v0 = alpha * acc[ni][2 * h]     + ((row == col)     ? beta : 0.f);
            float v1 = alpha * acc[ni][2 * h + 1] + ((row == col + 1) ? beta : 0.f);
            uint32_t hw = h2pack(v0, v1);
            B[row * PITCH32 + (col >> 1)] = hw;
            if (mir) {
                B16[col * PITCH16 + row]       = (uint16_t)hw;
                B16[(col + 1) * PITCH16 + row] = (uint16_t)(hw >> 16);
            }
        }
    }
}

__device__ __forceinline__ void epi_out(const float acc[4][4],
                                        float* __restrict__ Ob, float s,
                                        int r0, int c0, int lane) {
    const int qr = lane >> 2, cp = (lane & 3) * 2;
#pragma unroll
    for (int ni = 0; ni < 4; ni++) {
        const int col = c0 + ni * 8 + cp;
#pragma unroll
        for (int h = 0; h < 2; h++) {
            const int row = r0 + qr + h * 8;
            *(float2*)(Ob + row * 128 + col) =
                make_float2(s * acc[ni][2 * h], s * acc[ni][2 * h + 1]);
        }
    }
}

// m64 column-panels covering the lower triangle (rows r..r+63, cols c..c+31)
__device__ __constant__ int P64R[4] = {0, 64, 32, 64};
__device__ __constant__ int P64C[4] = {0, 0, 32, 64};
// m16 tails of the lower triangle: tiles (3,1) halves + (3,3) halves
__device__ __constant__ int T16R[4] = {96, 112, 96, 112};
__device__ __constant__ int T16C[4] = {32, 32, 96, 96};

__global__ void __launch_bounds__(NT, 2)
ns_p64f16_kernel(const float* __restrict__ A, float* __restrict__ Out) {
    extern __shared__ uint32_t sm[];
    uint32_t* Yb = sm;
    uint32_t* Zb = sm + 128 * PITCH32;
    uint32_t* Tb = sm + 2 * 128 * PITCH32;
    __shared__ float red[8];

    const int tid = threadIdx.x, w = tid >> 5, lane = tid & 31;
    const float* Ab = A + (size_t)blockIdx.x * 16384;
    float* Ob = Out + (size_t)blockIdx.x * 16384;

    // --- P1 / iter1: warps 0-3 m64 panels; warps 4-7 one m16 tail each ---
    const bool pbig = (w < 4);
    const int P1r = pbig ? P64R[w] : T16R[w - 4];
    const int P1c = pbig ? P64C[w] : T16C[w - 4];
    const bool P1tm = !pbig && (T16C[w - 4] == 32);  // tail mirror (tile 3,1)
    // --- P2: all warps m64 panel (w&3); Y for w<4, Z for w>=4.
    //     Warps 0-3 extra m32 tail: w0 Y(96,32), w1 Y(96,96), w2 Z(96,32), w3 Z(96,96)
    const int P2r = P64R[w & 3], P2c = P64C[w & 3];
    const bool p2z = (w >= 4);
    const bool p2tz = (w >= 2);
    const int P2tr = 96, P2tc = (w & 1) ? 96 : 32;
    const bool P2tm = !(w & 1);
    // --- last iter: m64 panel (r=(w&1)*64, c=(w>>1)*32) ---
    const int Lr = (w & 1) * 64, Lc = (w >> 1) * 32;

    // ---- Frobenius norm ----
    float ss = 0.f;
    const float4* A4 = (const float4*)Ab;
    for (int i = tid; i < 4096; i += NT) {
        float4 v = A4[i];
        ss = fmaf(v.x, v.x, fmaf(v.y, v.y, fmaf(v.z, v.z, fmaf(v.w, v.w, ss))));
    }
#pragma unroll
    for (int o = 16; o; o >>= 1) ss += __shfl_xor_sync(0xffffffffu, ss, o);
    if (lane == 0) red[w] = ss;
    __syncthreads();
    float tot = 0.f;
#pragma unroll
    for (int i = 0; i < 8; i++) tot += red[i];
    const float normA = sqrtf(tot);
    const float inv = 1.f / normA;

    // ---- Init: Y0 = f16(A*inv); T1 = Z1 = f16(1.5I - 0.5*Y0) ----
    for (int u = tid; u < 2048; u += NT) {
        const int row = u >> 4;
        const int col = (u & 15) * 8;
        float4 a0 = *(const float4*)(Ab + row * 128 + col);
        float4 a1 = *(const float4*)(Ab + row * 128 + col + 4);
        float yv[8] = {a0.x * inv, a0.y * inv, a0.z * inv, a0.w * inv,
                       a1.x * inv, a1.y * inv, a1.z * inv, a1.w * inv};
#pragma unroll
        for (int jj = 0; jj < 4; jj++) {
            const int cc = col + 2 * jj;
            const int idx = row * PITCH32 + (cc >> 1);
            Yb[idx] = h2pack(yv[2 * jj], yv[2 * jj + 1]);
            float t0 = -0.5f * yv[2 * jj]     + (row == cc     ? 1.5f : 0.f);
            float t1 = -0.5f * yv[2 * jj + 1] + (row == cc + 1 ? 1.5f : 0.f);
            uint32_t tb = h2pack(t0, t1);
            Tb[idx] = tb;
            Zb[idx] = tb;
        }
    }
    __syncthreads();

    float acc[4][4][4];

    // ---- iter 1 (reduced): Y = Y @ T1, triangular ----
    {
        if (pbig) {
            zero4(acc[0]); zero4(acc[1]); zero4(acc[2]); zero4(acc[3]);
            mm64(Yb, Tb, acc, P1r, P1c, lane);
        } else {
            zero4(acc[0]);
            mm16(Yb, Tb, acc[0], P1r, P1c, lane);
        }
        __syncthreads();
        if (pbig) {
#pragma unroll
            for (int g = 0; g < 4; g++) {
                const int rg = P1r + g * 16;
                epi_t(acc[g], Yb, 1.f, 0.f, rg, P1c, lane,
                      (rg >> 5) != (P1c >> 5));
            }
        } else {
            epi_t(acc[0], Yb, 1.f, 0.f, P1r, P1c, lane, P1tm);
        }
        __syncthreads();
    }

    // ---- iters 2..5 ----
#pragma unroll 1
    for (int it = 1; it < 5; ++it) {
        // P1: T = 1.5I - 0.5*(Z @ Y); epilogue fused (T not a P1 operand)
        {
            if (pbig) {
                zero4(acc[0]); zero4(acc[1]); zero4(acc[2]); zero4(acc[3]);
                mm64(Zb, Yb, acc, P1r, P1c, lane);
#pragma unroll
                for (int g = 0; g < 4; g++) {
                    const int rg = P1r + g * 16;
                    epi_t(acc[g], Tb, -0.5f, 1.5f, rg, P1c, lane,
                          (rg >> 5) != (P1c >> 5));
                }
            } else {
                zero4(acc[0]);
                mm16(Zb, Yb, acc[0], P1r, P1c, lane);
                epi_t(acc[0], Tb, -0.5f, 1.5f, P1r, P1c, lane, P1tm);
            }
        }
        __syncthreads();

        if (it < 4) {
            // P2: m64 panel (Y@T or Z@T) + m32 tails on warps 0-3
            zero4(acc[0]); zero4(acc[1]); zero4(acc[2]); zero4(acc[3]);
            mm64(p2z ? Zb : Yb, Tb, acc, P2r, P2c, lane);
            float acct[2][4][4];
            if (w < 4) {
                zero4(acct[0]); zero4(acct[1]);
                mm32(p2tz ? Zb : Yb, Tb, acct, P2tr, P2tc, lane);
            }
            __syncthreads();
            {
                uint32_t* D = p2z ? Zb : Yb;
#pragma unroll
                for (int g = 0; g < 4; g++) {
                    const int rg = P2r + g * 16;
                    epi_t(acc[g], D, 1.f, 0.f, rg, P2c, lane,
                          (rg >> 5) != (P2c >> 5));
                }
                if (w < 4) {
                    uint32_t* Dt = p2tz ? Zb : Yb;
                    epi_t(acct[0], Dt, 1.f, 0.f, P2tr, P2tc, lane, P2tm);
                    epi_t(acct[1], Dt, 1.f, 0.f, P2tr + 16, P2tc, lane, P2tm);
                }
            }
            __syncthreads();
        } else {
            // Last: Y5 = Y@T full grid (8 m64 panels), straight to GMEM
            const float s = sqrtf(normA);
            zero4(acc[0]); zero4(acc[1]); zero4(acc[2]); zero4(acc[3]);
            mm64(Yb, Tb, acc, Lr, Lc, lane);
#pragma unroll
            for (int g = 0; g < 4; g++)
                epi_out(acc[g], Ob, s, Lr + g * 16, Lc, lane);
        }
    }
}

extern "C" void kernel_launch(void* const* d_in, const int* in_sizes, int n_in,
                              void* d_out, int out_size) {
    const float* A = (const float*)d_in[0];
    float* out = (float*)d_out;
    const int nbatch = in_sizes[0] / (NMAT * NMAT);           // 1024
    const size_t smem = 3 * 128 * PITCH32 * sizeof(uint32_t); // 104448 B
    cudaFuncSetAttribute(ns_p64f16_kernel,
                         cudaFuncAttributeMaxDynamicSharedMemorySize, (int)smem);
    ns_p64f16_kernel<<<nbatch, NT, smem>>>(A, out);
}